// round 8
// baseline (speedup 1.0000x reference)
#include <cuda_runtime.h>
#include <math.h>

#define NUM_USERS 100000
#define NUM_ITEMS 50000
#define NROWS     150000      // NUM_USERS + NUM_ITEMS
#define NPAD      150016      // padded row count (multiple of 128)
#define EMB       64
#define NEDGES    2400000
#define NLAYERS   3
#define NEG_SLOPE 0.01f

#define SCAN_CHUNK 2048
#define NUM_CHUNKS ((NROWS + SCAN_CHUNK - 1) / SCAN_CHUNK)   // 74

typedef unsigned long long u64;

// packed fp32x2 FMA (Blackwell; ptxas never auto-fuses -> inline PTX)
#define FMA2(d, a, b, c) \
    asm("fma.rn.f32x2 %0, %1, %2, %3;" : "=l"(d) : "l"(a), "l"(b), "l"(c))
#define PACK2(d, lo, hi) \
    asm("mov.b64 %0, {%1, %2};" : "=l"(d) : "f"(lo), "f"(hi))
#define UNPACK2(lo, hi, v) \
    asm("mov.b64 {%0, %1}, %2;" : "=f"(lo), "=f"(hi) : "l"(v))

// -------- persistent device scratch (no allocations allowed) --------
__device__ __align__(16) float g_ego [NPAD * EMB];
__device__ __align__(16) float g_side[NPAD * EMB];
__device__ int   g_row_ptr[NROWS + 1];
__device__ int   g_cursor [NROWS];       // histogram counts, then scatter cursor
__device__ __align__(16) int2 g_edge[NEDGES + 2];  // (col, val-bits); +2 pad for int4 tail
__device__ int   g_bsum[NUM_CHUNKS];
__device__ int   g_boff[NUM_CHUNKS];

// ---------------------------------------------------------------
// setup: zero hist counters; ego = [user_emb; item_emb]; out[:,0:64] = ego
// ---------------------------------------------------------------
__global__ void k_setup(const float* __restrict__ user_emb,
                        const float* __restrict__ item_emb,
                        float* __restrict__ out) {
    int idx = blockIdx.x * blockDim.x + threadIdx.x;   // one float4 per thread
    if (idx < NROWS) g_cursor[idx] = 0;
    if (idx >= NROWS * 16) return;
    int r = idx >> 4;
    int c4 = idx & 15;
    float4 v;
    if (r < NUM_USERS)
        v = ((const float4*)&user_emb[r * EMB])[c4];
    else
        v = ((const float4*)&item_emb[(r - NUM_USERS) * EMB])[c4];
    ((float4*)&g_ego[r * EMB])[c4] = v;
    ((float4*)&out[r * (EMB * (NLAYERS + 1))])[c4] = v;
}

// ---------------------------------------------------------------
// CSR build
// ---------------------------------------------------------------
__global__ void k_hist(const int* __restrict__ rows, int n_edges) {
    int e = blockIdx.x * blockDim.x + threadIdx.x;
    if (e < n_edges) atomicAdd(&g_cursor[rows[e]], 1);
}

__global__ void k_scan_sums() {
    int b = blockIdx.x, t = threadIdx.x;
    int base = b * SCAN_CHUNK + t * 8;
    int s = 0;
#pragma unroll
    for (int i = 0; i < 8; i++) {
        int idx = base + i;
        if (idx < NROWS) s += g_cursor[idx];
    }
    __shared__ int sh[256];
    sh[t] = s;
    __syncthreads();
    for (int d = 128; d > 0; d >>= 1) {
        if (t < d) sh[t] += sh[t + d];
        __syncthreads();
    }
    if (t == 0) g_bsum[b] = sh[0];
}

__global__ void k_scan_top() {
    int t = threadIdx.x;
    __shared__ int sh[128];
    int v = (t < NUM_CHUNKS) ? g_bsum[t] : 0;
    sh[t] = v;
    __syncthreads();
    for (int d = 1; d < 128; d <<= 1) {
        int x = (t >= d) ? sh[t - d] : 0;
        __syncthreads();
        sh[t] += x;
        __syncthreads();
    }
    if (t < NUM_CHUNKS) g_boff[t] = sh[t] - v;
    if (t == NUM_CHUNKS - 1) g_row_ptr[NROWS] = sh[t];
}

__global__ void k_scan_final() {
    int b = blockIdx.x, t = threadIdx.x;
    int base = b * SCAN_CHUNK + t * 8;
    int v[8];
    int local = 0;
#pragma unroll
    for (int i = 0; i < 8; i++) {
        int idx = base + i;
        v[i] = (idx < NROWS) ? g_cursor[idx] : 0;
        local += v[i];
    }
    __shared__ int sh[256];
    sh[t] = local;
    __syncthreads();
    for (int d = 1; d < 256; d <<= 1) {
        int x = (t >= d) ? sh[t - d] : 0;
        __syncthreads();
        sh[t] += x;
        __syncthreads();
    }
    int exc = g_boff[b] + (t ? sh[t - 1] : 0);
#pragma unroll
    for (int i = 0; i < 8; i++) {
        int idx = base + i;
        if (idx < NROWS) {
            g_row_ptr[idx] = exc;
            g_cursor[idx]  = exc;
        }
        exc += v[i];
    }
}

__global__ void k_scatter(const int* __restrict__ rows,
                          const int* __restrict__ cols,
                          const float* __restrict__ vals, int n_edges) {
    int e = blockIdx.x * blockDim.x + threadIdx.x;
    if (e < n_edges) {
        int r = rows[e];
        int pos = atomicAdd(&g_cursor[r], 1);
        g_edge[pos] = make_int2(cols[e], __float_as_int(vals[e]));
    }
}

// ---------------------------------------------------------------
// SpMM: side = A @ ego  (warp per row, CSR; int4 loads = 2 edges/LDG)
// ---------------------------------------------------------------
__global__ void k_spmm() {
    int w = (blockIdx.x * blockDim.x + threadIdx.x) >> 5;
    int lane = threadIdx.x & 31;
    if (w >= NROWS) return;
    int s = g_row_ptr[w];
    int e = g_row_ptr[w + 1];

    float2 accA = make_float2(0.f, 0.f);
    float2 accB = make_float2(0.f, 0.f);

    int i = s;
    // alignment prologue: make i even so &g_edge[i] is 16B-aligned
    if ((i & 1) && i < e) {
        int2 ed = __ldg(&g_edge[i]);
        float v = __int_as_float(ed.y);
        float2 x = *(const float2*)&g_ego[ed.x * EMB + lane * 2];
        accA.x = fmaf(v, x.x, accA.x);
        accA.y = fmaf(v, x.y, accA.y);
        i++;
    }
    for (; i + 4 <= e; i += 4) {
        int4 e01 = __ldg((const int4*)&g_edge[i]);       // edges i, i+1
        int4 e23 = __ldg((const int4*)&g_edge[i + 2]);   // edges i+2, i+3
        float v0 = __int_as_float(e01.y);
        float v1 = __int_as_float(e01.w);
        float v2 = __int_as_float(e23.y);
        float v3 = __int_as_float(e23.w);
        float2 x0 = *(const float2*)&g_ego[e01.x * EMB + lane * 2];
        float2 x1 = *(const float2*)&g_ego[e01.z * EMB + lane * 2];
        float2 x2 = *(const float2*)&g_ego[e23.x * EMB + lane * 2];
        float2 x3 = *(const float2*)&g_ego[e23.z * EMB + lane * 2];
        accA.x = fmaf(v0, x0.x, accA.x); accA.y = fmaf(v0, x0.y, accA.y);
        accB.x = fmaf(v1, x1.x, accB.x); accB.y = fmaf(v1, x1.y, accB.y);
        accA.x = fmaf(v2, x2.x, accA.x); accA.y = fmaf(v2, x2.y, accA.y);
        accB.x = fmaf(v3, x3.x, accB.x); accB.y = fmaf(v3, x3.y, accB.y);
    }
    for (; i < e; i++) {
        int2 ed = __ldg(&g_edge[i]);
        float v = __int_as_float(ed.y);
        float2 x = *(const float2*)&g_ego[ed.x * EMB + lane * 2];
        accA.x = fmaf(v, x.x, accA.x);
        accA.y = fmaf(v, x.y, accA.y);
    }
    accA.x += accB.x;
    accA.y += accB.y;
    *(float2*)&g_side[w * EMB + lane * 2] = accA;
}

// ---------------------------------------------------------------
// Transform: ego = lrelu(side@W1+b1) + lrelu((ego*side)@W2+b2)
//            out[:, (l+1)*64 : (l+2)*64] = ego / max(||ego||, eps)
// 256 threads per 128 rows: thread computes 32 output cols of one row.
// (identical to the 577us R3 version)
// ---------------------------------------------------------------
__device__ __forceinline__ float lrelu(float a) {
    return (a > 0.f) ? a : NEG_SLOPE * a;
}

__global__ void __launch_bounds__(256)
k_transform(const float* __restrict__ W1g, const float* __restrict__ b1g,
            const float* __restrict__ W2g, const float* __restrict__ b2g,
            float* __restrict__ out, int layer) {
    extern __shared__ float sh[];
    float* W1s   = sh;                 // 4096
    float* W2s   = sh + 4096;          // 4096
    float* b1s   = sh + 8192;          // 64
    float* b2s   = sh + 8256;          // 64
    float* ssq   = sh + 8320;          // 256
    float* sideS = sh + 8576;          // 128*65 = 8320
    float* uS    = sideS + 128 * 65;   // 8320

    int t = threadIdx.x;
    int base = blockIdx.x * 128;

#pragma unroll 4
    for (int i = t; i < 1024; i += 256) {
        ((float4*)W1s)[i] = ((const float4*)W1g)[i];
        ((float4*)W2s)[i] = ((const float4*)W2g)[i];
    }
    if (t < 64) { b1s[t] = b1g[t]; b2s[t] = b2g[t]; }

    const float4* sg = (const float4*)&g_side[(size_t)base * EMB];
    const float4* eg = (const float4*)&g_ego [(size_t)base * EMB];
#pragma unroll 4
    for (int i = t; i < 2048; i += 256) {
        float4 sv = sg[i];
        float4 ev = eg[i];
        int row = i >> 4;
        int c = (i & 15) * 4;
        float* ds = &sideS[row * 65 + c];
        float* du = &uS   [row * 65 + c];
        ds[0] = sv.x; ds[1] = sv.y; ds[2] = sv.z; ds[3] = sv.w;
        du[0] = ev.x * sv.x; du[1] = ev.y * sv.y;
        du[2] = ev.z * sv.z; du[3] = ev.w * sv.w;
    }
    __syncthreads();

    int row = t & 127;
    int h   = t >> 7;
    int r   = base + row;

    float o[32];

    if (r < NROWS) {
        const float* srow = &sideS[row * 65];
        const float* urow = &uS[row * 65];

        u64 acc1[16], acc2[16];
#pragma unroll
        for (int j = 0; j < 16; j++) {
            PACK2(acc1[j], b1s[h * 32 + 2 * j], b1s[h * 32 + 2 * j + 1]);
            PACK2(acc2[j], b2s[h * 32 + 2 * j], b2s[h * 32 + 2 * j + 1]);
        }
#pragma unroll 4
        for (int k = 0; k < 64; k++) {
            float s = srow[k];
            float u = urow[k];
            u64 ss, uu;
            PACK2(ss, s, s);
            PACK2(uu, u, u);
            const u64* w1 = (const u64*)&W1s[k * 64 + h * 32];
            const u64* w2 = (const u64*)&W2s[k * 64 + h * 32];
#pragma unroll
            for (int j = 0; j < 16; j += 2) {
                ulonglong2 a = *(const ulonglong2*)&w1[j];
                FMA2(acc1[j],     ss, a.x, acc1[j]);
                FMA2(acc1[j + 1], ss, a.y, acc1[j + 1]);
                ulonglong2 b = *(const ulonglong2*)&w2[j];
                FMA2(acc2[j],     uu, b.x, acc2[j]);
                FMA2(acc2[j + 1], uu, b.y, acc2[j + 1]);
            }
        }

        float sumsq = 0.f;
#pragma unroll
        for (int j = 0; j < 16; j++) {
            float a0, a1, b0, b1;
            UNPACK2(a0, a1, acc1[j]);
            UNPACK2(b0, b1, acc2[j]);
            float o0 = lrelu(a0) + lrelu(b0);
            float o1 = lrelu(a1) + lrelu(b1);
            sumsq += o0 * o0 + o1 * o1;
            o[2 * j]     = o0;
            o[2 * j + 1] = o1;
        }
        ssq[t] = sumsq;

        float4* egor = (float4*)&g_ego[(size_t)r * EMB + h * 32];
#pragma unroll
        for (int j4 = 0; j4 < 8; j4++)
            egor[j4] = make_float4(o[j4 * 4], o[j4 * 4 + 1],
                                   o[j4 * 4 + 2], o[j4 * 4 + 3]);
    }
    __syncthreads();

    if (r < NROWS) {
        float total = ssq[row] + ssq[128 + row];
        float inv = 1.0f / fmaxf(sqrtf(total), 1e-12f);
        float4* orow = (float4*)&out[(size_t)r * (EMB * (NLAYERS + 1))
                                     + (layer + 1) * EMB + h * 32];
#pragma unroll
        for (int j4 = 0; j4 < 8; j4++)
            orow[j4] = make_float4(o[j4 * 4] * inv, o[j4 * 4 + 1] * inv,
                                   o[j4 * 4 + 2] * inv, o[j4 * 4 + 3] * inv);
    }
}

// ---------------------------------------------------------------
extern "C" void kernel_launch(void* const* d_in, const int* in_sizes, int n_in,
                              void* d_out, int out_size) {
    const int*   adj_rows = (const int*)  d_in[0];
    const int*   adj_cols = (const int*)  d_in[1];
    const float* adj_vals = (const float*)d_in[2];
    const float* user_emb = (const float*)d_in[3];
    const float* item_emb = (const float*)d_in[4];
    const float* gc_w     = (const float*)d_in[5];
    const float* gc_b     = (const float*)d_in[6];
    const float* bi_w     = (const float*)d_in[7];
    const float* bi_b     = (const float*)d_in[8];
    float*       out      = (float*)d_out;

    int n_edges = in_sizes[0];

    const int smem_bytes = 25216 * (int)sizeof(float); // 100864
    cudaFuncSetAttribute(k_transform, cudaFuncAttributeMaxDynamicSharedMemorySize, smem_bytes);

    // ---- setup (zero counters + init ego + layer-0 output) ----
    k_setup<<<(NROWS * 16 + 255) / 256, 256>>>(user_emb, item_emb, out);

    // ---- CSR build ----
    k_hist<<<(n_edges + 255) / 256, 256>>>(adj_rows, n_edges);
    k_scan_sums<<<NUM_CHUNKS, 256>>>();
    k_scan_top<<<1, 128>>>();
    k_scan_final<<<NUM_CHUNKS, 256>>>();
    k_scatter<<<(n_edges + 255) / 256, 256>>>(adj_rows, adj_cols, adj_vals, n_edges);

    // ---- layers ----
    int spmm_blocks = (NROWS * 32 + 255) / 256;        // warp per row
    int tr_blocks   = (NROWS + 127) / 128;
    for (int l = 0; l < NLAYERS; l++) {
        k_spmm<<<spmm_blocks, 256>>>();
        k_transform<<<tr_blocks, 256, smem_bytes>>>(
            gc_w + l * 4096, gc_b + l * 64,
            bi_w + l * 4096, bi_b + l * 64,
            out, l);
    }
}

// round 9
// speedup vs baseline: 1.1007x; 1.1007x over previous
#include <cuda_runtime.h>
#include <math.h>

#define NUM_USERS 100000
#define NUM_ITEMS 50000
#define NROWS     150000      // NUM_USERS + NUM_ITEMS
#define NPAD      150016      // padded row count (multiple of 128)
#define EMB       64
#define NEDGES    2400000
#define NLAYERS   3
#define NEG_SLOPE 0.01f

#define SCAN_CHUNK 2048
#define NUM_CHUNKS ((NROWS + SCAN_CHUNK - 1) / SCAN_CHUNK)   // 74

typedef unsigned long long u64;

// packed fp32x2 FMA (Blackwell; ptxas never auto-fuses -> inline PTX)
#define FMA2(d, a, b, c) \
    asm("fma.rn.f32x2 %0, %1, %2, %3;" : "=l"(d) : "l"(a), "l"(b), "l"(c))
#define PACK2(d, lo, hi) \
    asm("mov.b64 %0, {%1, %2};" : "=l"(d) : "f"(lo), "f"(hi))
#define UNPACK2(lo, hi, v) \
    asm("mov.b64 {%0, %1}, %2;" : "=f"(lo), "=f"(hi) : "l"(v))

// -------- persistent device scratch (no allocations allowed) --------
__device__ __align__(16) float g_ego [NPAD * EMB];
__device__ __align__(16) float g_side[NPAD * EMB];
__device__ int   g_row_ptr[NROWS + 1];
__device__ int   g_cursor [NROWS];        // zeroed by transform(layer 0) of the PREVIOUS run
__device__ int   g_col [NEDGES];
__device__ float g_val [NEDGES];
// decoupled-lookback scan state: (flag<<32:62) | value. 0=empty, 1=agg, 2=prefix.
// zeroed by k_scatter of the SAME run (after scan completes), so next replay is clean.
__device__ volatile u64 g_scan_state[NUM_CHUNKS];

// ---------------------------------------------------------------
// Launch 0: hist (atomics into cursor) + ego init + out layer-0.
// grid: 2.4M threads = NEDGES = NROWS*16 exactly.
// ---------------------------------------------------------------
__global__ void k_hist_init(const int* __restrict__ rows,
                            const float* __restrict__ user_emb,
                            const float* __restrict__ item_emb,
                            float* __restrict__ out, int n_edges) {
    int idx = blockIdx.x * blockDim.x + threadIdx.x;
    if (idx < n_edges) atomicAdd(&g_cursor[rows[idx]], 1);
    if (idx >= NROWS * 16) return;
    int r = idx >> 4;
    int c4 = idx & 15;
    float4 v;
    if (r < NUM_USERS)
        v = ((const float4*)&user_emb[r * EMB])[c4];
    else
        v = ((const float4*)&item_emb[(r - NUM_USERS) * EMB])[c4];
    ((float4*)&g_ego[r * EMB])[c4] = v;
    ((float4*)&out[r * (EMB * (NLAYERS + 1))])[c4] = v;
}

// ---------------------------------------------------------------
// Launch 1: single-kernel exclusive scan (decoupled lookback, 74 blocks).
// Writes g_row_ptr and g_cursor (scatter cursor).
// ---------------------------------------------------------------
__global__ void __launch_bounds__(256) k_scan() {
    int b = blockIdx.x, t = threadIdx.x;
    int base = b * SCAN_CHUNK + t * 8;
    int v[8];
    int local = 0;
#pragma unroll
    for (int i = 0; i < 8; i++) {
        int idx = base + i;
        v[i] = (idx < NROWS) ? g_cursor[idx] : 0;
        local += v[i];
    }
    __shared__ int sh[256];
    __shared__ int s_prev;
    sh[t] = local;
    __syncthreads();
    for (int d = 1; d < 256; d <<= 1) {
        int x = (t >= d) ? sh[t - d] : 0;
        __syncthreads();
        sh[t] += x;
        __syncthreads();
    }
    // thread 255 publishes aggregate / resolves prefix via lookback
    if (t == 255) {
        u64 agg = (u64)(unsigned)sh[255];
        if (b == 0) {
            g_scan_state[0] = (2ull << 62) | agg;   // prefix known = agg
            s_prev = 0;
        } else {
            g_scan_state[b] = (1ull << 62) | agg;   // aggregate available
            int prev = 0;
            int j = b - 1;
            while (j >= 0) {
                u64 st;
                do { st = g_scan_state[j]; } while ((st >> 62) == 0);
                if ((st >> 62) == 2ull) { prev += (int)(unsigned)st; break; }
                prev += (int)(unsigned)st;
                j--;
            }
            g_scan_state[b] = (2ull << 62) | (u64)(unsigned)(prev + sh[255]);
            s_prev = prev;
        }
    }
    __syncthreads();

    int exc = s_prev + (t ? sh[t - 1] : 0);
#pragma unroll
    for (int i = 0; i < 8; i++) {
        int idx = base + i;
        if (idx < NROWS) {
            g_row_ptr[idx] = exc;
            g_cursor[idx]  = exc;
        }
        exc += v[i];
    }
    if (b == NUM_CHUNKS - 1 && t == 255)
        g_row_ptr[NROWS] = s_prev + sh[255];
}

// ---------------------------------------------------------------
// Launch 2: scatter edges into CSR slots; also clear scan state for next run.
// ---------------------------------------------------------------
__global__ void k_scatter(const int* __restrict__ rows,
                          const int* __restrict__ cols,
                          const float* __restrict__ vals, int n_edges) {
    int e = blockIdx.x * blockDim.x + threadIdx.x;
    if (e < NUM_CHUNKS) g_scan_state[e] = 0;       // safe: scan already complete
    if (e < n_edges) {
        int r = rows[e];
        int pos = atomicAdd(&g_cursor[r], 1);
        g_col[pos] = cols[e];
        g_val[pos] = vals[e];
    }
}

// ---------------------------------------------------------------
// Launch 3 (PROFILED by ncu): SpMM side = A @ ego — proven 577us version
// ---------------------------------------------------------------
__global__ void k_spmm() {
    int w = (blockIdx.x * blockDim.x + threadIdx.x) >> 5;
    int lane = threadIdx.x & 31;
    if (w >= NROWS) return;
    int s = g_row_ptr[w];
    int e = g_row_ptr[w + 1];
    float2 acc = make_float2(0.f, 0.f);
    for (int i = s; i < e; i++) {
        int c = __ldg(&g_col[i]);
        float v = __ldg(&g_val[i]);
        float2 x = *(const float2*)&g_ego[c * EMB + lane * 2];
        acc.x = fmaf(v, x.x, acc.x);
        acc.y = fmaf(v, x.y, acc.y);
    }
    *(float2*)&g_side[w * EMB + lane * 2] = acc;
}

// ---------------------------------------------------------------
// Transform (R3 proven version) + layer-0 cursor re-zero for next replay
// ---------------------------------------------------------------
__device__ __forceinline__ float lrelu(float a) {
    return (a > 0.f) ? a : NEG_SLOPE * a;
}

__global__ void __launch_bounds__(256)
k_transform(const float* __restrict__ W1g, const float* __restrict__ b1g,
            const float* __restrict__ W2g, const float* __restrict__ b2g,
            float* __restrict__ out, int layer) {
    extern __shared__ float sh[];
    float* W1s   = sh;                 // 4096
    float* W2s   = sh + 4096;          // 4096
    float* b1s   = sh + 8192;          // 64
    float* b2s   = sh + 8256;          // 64
    float* ssq   = sh + 8320;          // 256
    float* sideS = sh + 8576;          // 128*65 = 8320
    float* uS    = sideS + 128 * 65;   // 8320

    int t = threadIdx.x;
    int base = blockIdx.x * 128;

#pragma unroll 4
    for (int i = t; i < 1024; i += 256) {
        ((float4*)W1s)[i] = ((const float4*)W1g)[i];
        ((float4*)W2s)[i] = ((const float4*)W2g)[i];
    }
    if (t < 64) { b1s[t] = b1g[t]; b2s[t] = b2g[t]; }

    const float4* sg = (const float4*)&g_side[(size_t)base * EMB];
    const float4* eg = (const float4*)&g_ego [(size_t)base * EMB];
#pragma unroll 4
    for (int i = t; i < 2048; i += 256) {
        float4 sv = sg[i];
        float4 ev = eg[i];
        int row = i >> 4;
        int c = (i & 15) * 4;
        float* ds = &sideS[row * 65 + c];
        float* du = &uS   [row * 65 + c];
        ds[0] = sv.x; ds[1] = sv.y; ds[2] = sv.z; ds[3] = sv.w;
        du[0] = ev.x * sv.x; du[1] = ev.y * sv.y;
        du[2] = ev.z * sv.z; du[3] = ev.w * sv.w;
    }
    __syncthreads();

    int row = t & 127;
    int h   = t >> 7;
    int r   = base + row;

    // re-zero histogram counters for the next replay (cursor is dead now)
    if (layer == 0 && h == 0 && r < NROWS) g_cursor[r] = 0;

    float o[32];

    if (r < NROWS) {
        const float* srow = &sideS[row * 65];
        const float* urow = &uS[row * 65];

        u64 acc1[16], acc2[16];
#pragma unroll
        for (int j = 0; j < 16; j++) {
            PACK2(acc1[j], b1s[h * 32 + 2 * j], b1s[h * 32 + 2 * j + 1]);
            PACK2(acc2[j], b2s[h * 32 + 2 * j], b2s[h * 32 + 2 * j + 1]);
        }
#pragma unroll 4
        for (int k = 0; k < 64; k++) {
            float s = srow[k];
            float u = urow[k];
            u64 ss, uu;
            PACK2(ss, s, s);
            PACK2(uu, u, u);
            const u64* w1 = (const u64*)&W1s[k * 64 + h * 32];
            const u64* w2 = (const u64*)&W2s[k * 64 + h * 32];
#pragma unroll
            for (int j = 0; j < 16; j += 2) {
                ulonglong2 a = *(const ulonglong2*)&w1[j];
                FMA2(acc1[j],     ss, a.x, acc1[j]);
                FMA2(acc1[j + 1], ss, a.y, acc1[j + 1]);
                ulonglong2 b = *(const ulonglong2*)&w2[j];
                FMA2(acc2[j],     uu, b.x, acc2[j]);
                FMA2(acc2[j + 1], uu, b.y, acc2[j + 1]);
            }
        }

        float sumsq = 0.f;
#pragma unroll
        for (int j = 0; j < 16; j++) {
            float a0, a1, b0, b1;
            UNPACK2(a0, a1, acc1[j]);
            UNPACK2(b0, b1, acc2[j]);
            float o0 = lrelu(a0) + lrelu(b0);
            float o1 = lrelu(a1) + lrelu(b1);
            sumsq += o0 * o0 + o1 * o1;
            o[2 * j]     = o0;
            o[2 * j + 1] = o1;
        }
        ssq[t] = sumsq;

        float4* egor = (float4*)&g_ego[(size_t)r * EMB + h * 32];
#pragma unroll
        for (int j4 = 0; j4 < 8; j4++)
            egor[j4] = make_float4(o[j4 * 4], o[j4 * 4 + 1],
                                   o[j4 * 4 + 2], o[j4 * 4 + 3]);
    }
    __syncthreads();

    if (r < NROWS) {
        float total = ssq[row] + ssq[128 + row];
        float inv = 1.0f / fmaxf(sqrtf(total), 1e-12f);
        float4* orow = (float4*)&out[(size_t)r * (EMB * (NLAYERS + 1))
                                     + (layer + 1) * EMB + h * 32];
#pragma unroll
        for (int j4 = 0; j4 < 8; j4++)
            orow[j4] = make_float4(o[j4 * 4] * inv, o[j4 * 4 + 1] * inv,
                                   o[j4 * 4 + 2] * inv, o[j4 * 4 + 3] * inv);
    }
}

// ---------------------------------------------------------------
extern "C" void kernel_launch(void* const* d_in, const int* in_sizes, int n_in,
                              void* d_out, int out_size) {
    const int*   adj_rows = (const int*)  d_in[0];
    const int*   adj_cols = (const int*)  d_in[1];
    const float* adj_vals = (const float*)d_in[2];
    const float* user_emb = (const float*)d_in[3];
    const float* item_emb = (const float*)d_in[4];
    const float* gc_w     = (const float*)d_in[5];
    const float* gc_b     = (const float*)d_in[6];
    const float* bi_w     = (const float*)d_in[7];
    const float* bi_b     = (const float*)d_in[8];
    float*       out      = (float*)d_out;

    int n_edges = in_sizes[0];

    const int smem_bytes = 25216 * (int)sizeof(float); // 100864
    cudaFuncSetAttribute(k_transform, cudaFuncAttributeMaxDynamicSharedMemorySize, smem_bytes);

    // launch 0: hist + ego init + layer-0 out
    k_hist_init<<<(n_edges + 255) / 256, 256>>>(adj_rows, user_emb, item_emb,
                                                out, n_edges);
    // launch 1: single-kernel scan
    k_scan<<<NUM_CHUNKS, 256>>>();
    // launch 2: scatter (+ scan-state cleanup)
    k_scatter<<<(n_edges + 255) / 256, 256>>>(adj_rows, adj_cols, adj_vals, n_edges);

    // launches 3..8: layers (spmm is launch index 3 -> profiled by ncu)
    int spmm_blocks = (NROWS * 32 + 255) / 256;        // warp per row
    int tr_blocks   = (NROWS + 127) / 128;
    for (int l = 0; l < NLAYERS; l++) {
        k_spmm<<<spmm_blocks, 256>>>();
        k_transform<<<tr_blocks, 256, smem_bytes>>>(
            gc_w + l * 4096, gc_b + l * 64,
            bi_w + l * 4096, bi_b + l * 64,
            out, l);
    }
}

// round 10
// speedup vs baseline: 1.1626x; 1.0562x over previous
#include <cuda_runtime.h>
#include <math.h>

#define NUM_USERS 100000
#define NUM_ITEMS 50000
#define NROWS     150000      // NUM_USERS + NUM_ITEMS
#define NPAD      150016      // padded row count
#define EMB       64
#define NEDGES    2400000
#define NLAYERS   3
#define NEG_SLOPE 0.01f

#define SCAN_CHUNK 2048
#define NUM_CHUNKS ((NROWS + SCAN_CHUNK - 1) / SCAN_CHUNK)   // 74

typedef unsigned long long u64;

// packed fp32x2 FMA (Blackwell; ptxas never auto-fuses -> inline PTX)
#define FMA2(d, a, b, c) \
    asm("fma.rn.f32x2 %0, %1, %2, %3;" : "=l"(d) : "l"(a), "l"(b), "l"(c))
#define PACK2(d, lo, hi) \
    asm("mov.b64 %0, {%1, %2};" : "=l"(d) : "f"(lo), "f"(hi))
#define UNPACK2(lo, hi, v) \
    asm("mov.b64 {%0, %1}, %2;" : "=f"(lo), "=f"(hi) : "l"(v))

// -------- persistent device scratch (no allocations allowed) --------
__device__ __align__(16) float g_ego [NPAD * EMB];
__device__ __align__(16) float g_side[NPAD * EMB];
__device__ int  g_row_ptr[NROWS + 1];
__device__ int  g_cursor [NROWS];        // zeroed by transform(layer 0) for next replay
__device__ __align__(16) int2 g_edge[NEDGES];  // (col, val-bits)
// decoupled-lookback scan state; zeroed by k_scatter after scan completes.
__device__ volatile u64 g_scan_state[NUM_CHUNKS];

// ---------------------------------------------------------------
// Launch 0: hist (atomics into cursor) + ego init + out layer-0.
// ---------------------------------------------------------------
__global__ void k_hist_init(const int* __restrict__ rows,
                            const float* __restrict__ user_emb,
                            const float* __restrict__ item_emb,
                            float* __restrict__ out, int n_edges) {
    int idx = blockIdx.x * blockDim.x + threadIdx.x;
    if (idx < n_edges) atomicAdd(&g_cursor[rows[idx]], 1);
    if (idx >= NROWS * 16) return;
    int r = idx >> 4;
    int c4 = idx & 15;
    float4 v;
    if (r < NUM_USERS)
        v = ((const float4*)&user_emb[r * EMB])[c4];
    else
        v = ((const float4*)&item_emb[(r - NUM_USERS) * EMB])[c4];
    ((float4*)&g_ego[r * EMB])[c4] = v;
    ((float4*)&out[r * (EMB * (NLAYERS + 1))])[c4] = v;
}

// ---------------------------------------------------------------
// Launch 1: single-kernel exclusive scan (decoupled lookback, 74 blocks).
// ---------------------------------------------------------------
__global__ void __launch_bounds__(256) k_scan() {
    int b = blockIdx.x, t = threadIdx.x;
    int base = b * SCAN_CHUNK + t * 8;
    int v[8];
    int local = 0;
#pragma unroll
    for (int i = 0; i < 8; i++) {
        int idx = base + i;
        v[i] = (idx < NROWS) ? g_cursor[idx] : 0;
        local += v[i];
    }
    __shared__ int sh[256];
    __shared__ int s_prev;
    sh[t] = local;
    __syncthreads();
    for (int d = 1; d < 256; d <<= 1) {
        int x = (t >= d) ? sh[t - d] : 0;
        __syncthreads();
        sh[t] += x;
        __syncthreads();
    }
    if (t == 255) {
        u64 agg = (u64)(unsigned)sh[255];
        if (b == 0) {
            g_scan_state[0] = (2ull << 62) | agg;
            s_prev = 0;
        } else {
            g_scan_state[b] = (1ull << 62) | agg;
            int prev = 0;
            int j = b - 1;
            while (j >= 0) {
                u64 st;
                do { st = g_scan_state[j]; } while ((st >> 62) == 0);
                if ((st >> 62) == 2ull) { prev += (int)(unsigned)st; break; }
                prev += (int)(unsigned)st;
                j--;
            }
            g_scan_state[b] = (2ull << 62) | (u64)(unsigned)(prev + sh[255]);
            s_prev = prev;
        }
    }
    __syncthreads();

    int exc = s_prev + (t ? sh[t - 1] : 0);
#pragma unroll
    for (int i = 0; i < 8; i++) {
        int idx = base + i;
        if (idx < NROWS) {
            g_row_ptr[idx] = exc;
            g_cursor[idx]  = exc;
        }
        exc += v[i];
    }
    if (b == NUM_CHUNKS - 1 && t == 255)
        g_row_ptr[NROWS] = s_prev + sh[255];
}

// ---------------------------------------------------------------
// Launch 2: scatter edges (int2: one 8B sector) + clear scan state.
// ---------------------------------------------------------------
__global__ void k_scatter(const int* __restrict__ rows,
                          const int* __restrict__ cols,
                          const float* __restrict__ vals, int n_edges) {
    int e = blockIdx.x * blockDim.x + threadIdx.x;
    if (e < NUM_CHUNKS) g_scan_state[e] = 0;
    if (e < n_edges) {
        int r = rows[e];
        int pos = atomicAdd(&g_cursor[r], 1);
        g_edge[pos] = make_int2(cols[e], __float_as_int(vals[e]));
    }
}

// ---------------------------------------------------------------
// Launch 3 (profiled): SpMM side = A @ ego, warp per row, int2 edges
// ---------------------------------------------------------------
__global__ void k_spmm() {
    int w = (blockIdx.x * blockDim.x + threadIdx.x) >> 5;
    int lane = threadIdx.x & 31;
    if (w >= NROWS) return;
    int s = g_row_ptr[w];
    int e = g_row_ptr[w + 1];
    float2 acc = make_float2(0.f, 0.f);
    for (int i = s; i < e; i++) {
        int2 ed = __ldg(&g_edge[i]);
        float v = __int_as_float(ed.y);
        float2 x = *(const float2*)&g_ego[ed.x * EMB + lane * 2];
        acc.x = fmaf(v, x.x, acc.x);
        acc.y = fmaf(v, x.y, acc.y);
    }
    *(float2*)&g_side[w * EMB + lane * 2] = acc;
}

// ---------------------------------------------------------------
// Transform: 64-row blocks, 256 threads, thread computes 16 cols of one row.
// q = t>>6 selects col quarter. smem 67.6KB -> 3 blocks/SM (24 warps).
// ---------------------------------------------------------------
__device__ __forceinline__ float lrelu(float a) {
    return (a > 0.f) ? a : NEG_SLOPE * a;
}

__global__ void __launch_bounds__(256)
k_transform(const float* __restrict__ W1g, const float* __restrict__ b1g,
            const float* __restrict__ W2g, const float* __restrict__ b2g,
            float* __restrict__ out, int layer) {
    extern __shared__ float sh[];
    float* W1s   = sh;                 // 4096
    float* W2s   = sh + 4096;          // 4096
    float* b1s   = sh + 8192;          // 64
    float* b2s   = sh + 8256;          // 64
    float* ssq   = sh + 8320;          // 256
    float* sideS = sh + 8576;          // 64*65 = 4160
    float* uS    = sideS + 4160;       // 4160
    // total = 16896 floats = 67584 bytes

    int t = threadIdx.x;
    int base = blockIdx.x * 64;

#pragma unroll 4
    for (int i = t; i < 1024; i += 256) {
        ((float4*)W1s)[i] = ((const float4*)W1g)[i];
        ((float4*)W2s)[i] = ((const float4*)W2g)[i];
    }
    if (t < 64) { b1s[t] = b1g[t]; b2s[t] = b2g[t]; }

    // stage side + u = ego*side for the block's 64 rows (padded stride 65)
    const float4* sg = (const float4*)&g_side[(size_t)base * EMB];
    const float4* eg = (const float4*)&g_ego [(size_t)base * EMB];
#pragma unroll 4
    for (int i = t; i < 1024; i += 256) {
        float4 sv = sg[i];
        float4 ev = eg[i];
        int row = i >> 4;
        int c = (i & 15) * 4;
        float* ds = &sideS[row * 65 + c];
        float* du = &uS   [row * 65 + c];
        ds[0] = sv.x; ds[1] = sv.y; ds[2] = sv.z; ds[3] = sv.w;
        du[0] = ev.x * sv.x; du[1] = ev.y * sv.y;
        du[2] = ev.z * sv.z; du[3] = ev.w * sv.w;
    }
    __syncthreads();

    int row = t & 63;         // row within block
    int q   = t >> 6;         // col quarter: cols q*16 .. q*16+15
    int r   = base + row;

    // re-zero histogram counters for next replay (cursor dead by now)
    if (layer == 0 && q == 0 && r < NROWS) g_cursor[r] = 0;

    float o[16];

    if (r < NROWS) {
        const float* srow = &sideS[row * 65];
        const float* urow = &uS[row * 65];

        u64 acc1[8], acc2[8];
#pragma unroll
        for (int j = 0; j < 8; j++) {
            PACK2(acc1[j], b1s[q * 16 + 2 * j], b1s[q * 16 + 2 * j + 1]);
            PACK2(acc2[j], b2s[q * 16 + 2 * j], b2s[q * 16 + 2 * j + 1]);
        }
#pragma unroll 4
        for (int k = 0; k < 64; k++) {
            float s = srow[k];
            float u = urow[k];
            u64 ss, uu;
            PACK2(ss, s, s);
            PACK2(uu, u, u);
            const u64* w1 = (const u64*)&W1s[k * 64 + q * 16];
            const u64* w2 = (const u64*)&W2s[k * 64 + q * 16];
#pragma unroll
            for (int j = 0; j < 8; j += 2) {
                ulonglong2 a = *(const ulonglong2*)&w1[j];
                FMA2(acc1[j],     ss, a.x, acc1[j]);
                FMA2(acc1[j + 1], ss, a.y, acc1[j + 1]);
                ulonglong2 b = *(const ulonglong2*)&w2[j];
                FMA2(acc2[j],     uu, b.x, acc2[j]);
                FMA2(acc2[j + 1], uu, b.y, acc2[j + 1]);
            }
        }

        float sumsq = 0.f;
#pragma unroll
        for (int j = 0; j < 8; j++) {
            float a0, a1, b0, b1;
            UNPACK2(a0, a1, acc1[j]);
            UNPACK2(b0, b1, acc2[j]);
            float o0 = lrelu(a0) + lrelu(b0);
            float o1 = lrelu(a1) + lrelu(b1);
            sumsq += o0 * o0 + o1 * o1;
            o[2 * j]     = o0;
            o[2 * j + 1] = o1;
        }
        ssq[t] = sumsq;   // t = q*64 + row

        float4* egor = (float4*)&g_ego[(size_t)r * EMB + q * 16];
#pragma unroll
        for (int j4 = 0; j4 < 4; j4++)
            egor[j4] = make_float4(o[j4 * 4], o[j4 * 4 + 1],
                                   o[j4 * 4 + 2], o[j4 * 4 + 3]);
    }
    __syncthreads();

    if (r < NROWS) {
        float total = ssq[row] + ssq[64 + row] + ssq[128 + row] + ssq[192 + row];
        float inv = 1.0f / fmaxf(sqrtf(total), 1e-12f);
        float4* orow = (float4*)&out[(size_t)r * (EMB * (NLAYERS + 1))
                                     + (layer + 1) * EMB + q * 16];
#pragma unroll
        for (int j4 = 0; j4 < 4; j4++)
            orow[j4] = make_float4(o[j4 * 4] * inv, o[j4 * 4 + 1] * inv,
                                   o[j4 * 4 + 2] * inv, o[j4 * 4 + 3] * inv);
    }
}

// ---------------------------------------------------------------
extern "C" void kernel_launch(void* const* d_in, const int* in_sizes, int n_in,
                              void* d_out, int out_size) {
    const int*   adj_rows = (const int*)  d_in[0];
    const int*   adj_cols = (const int*)  d_in[1];
    const float* adj_vals = (const float*)d_in[2];
    const float* user_emb = (const float*)d_in[3];
    const float* item_emb = (const float*)d_in[4];
    const float* gc_w     = (const float*)d_in[5];
    const float* gc_b     = (const float*)d_in[6];
    const float* bi_w     = (const float*)d_in[7];
    const float* bi_b     = (const float*)d_in[8];
    float*       out      = (float*)d_out;

    int n_edges = in_sizes[0];

    const int smem_bytes = 16896 * (int)sizeof(float); // 67584
    cudaFuncSetAttribute(k_transform, cudaFuncAttributeMaxDynamicSharedMemorySize, smem_bytes);

    // launch 0: hist + ego init + layer-0 out
    k_hist_init<<<(n_edges + 255) / 256, 256>>>(adj_rows, user_emb, item_emb,
                                                out, n_edges);
    // launch 1: single-kernel scan
    k_scan<<<NUM_CHUNKS, 256>>>();
    // launch 2: scatter (+ scan-state cleanup)
    k_scatter<<<(n_edges + 255) / 256, 256>>>(adj_rows, adj_cols, adj_vals, n_edges);

    // launches 3..8: layers (spmm at index 3 -> profiled)
    int spmm_blocks = (NROWS * 32 + 255) / 256;        // warp per row
    int tr_blocks   = (NROWS + 63) / 64;
    for (int l = 0; l < NLAYERS; l++) {
        k_spmm<<<spmm_blocks, 256>>>();
        k_transform<<<tr_blocks, 256, smem_bytes>>>(
            gc_w + l * 4096, gc_b + l * 64,
            bi_w + l * 4096, bi_b + l * 64,
            out, l);
    }
}